// round 1
// baseline (speedup 1.0000x reference)
#include <cuda_runtime.h>
#include <math.h>

// Problem constants
#define Bb 4
#define Cc 512      // IN_DIM
#define Tt 4096
#define Ee 1024     // EMBED
#define Hh 16
#define Dd 64
#define Ff 256
#define CO 1536     // output channels = Cc + Ee
#define EPS 1e-6f

// ---------------- scratch (device globals; no allocs allowed) ----------------
__device__ float g_Q   [Bb*Tt*Ee];      // 64 MB
__device__ float g_K   [Bb*Tt*Ee];      // 64 MB
__device__ float g_V   [Bb*Tt*Ee];      // 64 MB
__device__ float g_attn[Bb*Tt*Ee];      // 64 MB
__device__ float g_Qp  [Bb*Tt*Hh*Ff];   // 256 MB
__device__ float g_Kp  [Bb*Tt*Hh*Ff];   // 256 MB
__device__ float g_KV  [Bb*Hh*Ff*Dd];   // 4 MB
__device__ float g_Ksum[Bb*Hh*Ff];      // 256 KB

// ---------------- zero accumulators ----------------
__global__ void k_zero() {
    int i = blockIdx.x * 256 + threadIdx.x;
    if (i < Bb*Hh*Ff*Dd) g_KV[i] = 0.f;
    if (i < Bb*Hh*Ff)    g_Ksum[i] = 0.f;
}

// ---------------- copy x into out channels [0,512) ----------------
__global__ void k_copy(const float* __restrict__ x, float* __restrict__ out) {
    int i = blockIdx.x * 256 + threadIdx.x;      // over B*C*T/4 float4s
    const int per_b = Cc * Tt / 4;               // 524288
    int b = i / per_b, r = i % per_b;
    const float4* x4 = (const float4*)x;
    float4* o4 = (float4*)out;
    o4[(size_t)b * (CO*Tt/4) + r] = x4[(size_t)b * per_b + r];
}

// ---------------- K1: Q/K/V = Xbt @ W (M=16384, N=1024, K=512) ----------------
// x is (B, C, T): A[m=t][k=c] is k-major in memory -> As[k][m] loads are direct & coalesced.
__global__ __launch_bounds__(256) void k_qkv(const float* __restrict__ x,
                                             const float* __restrict__ Wq,
                                             const float* __restrict__ Wk,
                                             const float* __restrict__ Wv) {
    const float* W = blockIdx.z == 0 ? Wq : (blockIdx.z == 1 ? Wk : Wv);
    float* out = blockIdx.z == 0 ? g_Q : (blockIdx.z == 1 ? g_K : g_V);
    int m0 = blockIdx.x * 128;           // over B*T (128 | T, so single b per tile)
    int n0 = blockIdx.y * 128;
    int b = m0 / Tt, t0 = m0 % Tt;
    const float* xb = x + (size_t)b * Cc * Tt + t0;   // xb[k*Tt + m]

    __shared__ float As[16][128];
    __shared__ float Bs[16][128];
    int tid = threadIdx.x;
    int tx = tid & 15, ty = tid >> 4;

    float acc[8][8];
#pragma unroll
    for (int i = 0; i < 8; i++)
#pragma unroll
        for (int j = 0; j < 8; j++) acc[i][j] = 0.f;

    for (int k0 = 0; k0 < Cc; k0 += 16) {
#pragma unroll
        for (int i = tid; i < 2048; i += 256) {
            int k = i >> 7, m = i & 127;
            As[k][m] = xb[(size_t)(k0 + k) * Tt + m];
            Bs[k][m] = W[(size_t)(k0 + k) * Ee + n0 + m];
        }
        __syncthreads();
#pragma unroll
        for (int k = 0; k < 16; k++) {
            float a[8], bb[8];
            *(float4*)(a)     = *(const float4*)&As[k][ty*8];
            *(float4*)(a + 4) = *(const float4*)&As[k][ty*8 + 4];
            *(float4*)(bb)     = *(const float4*)&Bs[k][tx*8];
            *(float4*)(bb + 4) = *(const float4*)&Bs[k][tx*8 + 4];
#pragma unroll
            for (int i = 0; i < 8; i++)
#pragma unroll
                for (int j = 0; j < 8; j++) acc[i][j] += a[i] * bb[j];
        }
        __syncthreads();
    }
#pragma unroll
    for (int i = 0; i < 8; i++) {
        size_t row = (size_t)(m0 + ty*8 + i) * Ee + n0 + tx*8;
        float4 v0 = {acc[i][0], acc[i][1], acc[i][2], acc[i][3]};
        float4 v1 = {acc[i][4], acc[i][5], acc[i][6], acc[i][7]};
        *(float4*)&out[row]     = v0;
        *(float4*)&out[row + 4] = v1;
    }
}

// ---------------- K2: Qp/Kp = exp(QorK @ projT) + eps  (M=262144, N=256, K=64) ----------------
// A viewed as (B*T*H, 64) row-major -> keep As in [m][k] layout (no transpose needed).
__global__ __launch_bounds__(256) void k_feat(const float* __restrict__ proj) {
    const float* A = blockIdx.z == 0 ? g_Q : g_K;
    float* outp    = blockIdx.z == 0 ? g_Qp : g_Kp;
    int m0 = blockIdx.x * 128;   // over B*T*H
    int n0 = blockIdx.y * 128;   // over F

    __shared__ float As[128][32];     // [m][k]
    __shared__ float BsT[32][132];    // [k][n], padded for STS conflicts + alignment
    int tid = threadIdx.x;
    int tx = tid & 15, ty = tid >> 4;

    float acc[8][8];
#pragma unroll
    for (int i = 0; i < 8; i++)
#pragma unroll
        for (int j = 0; j < 8; j++) acc[i][j] = 0.f;

    for (int k0 = 0; k0 < 64; k0 += 32) {
#pragma unroll
        for (int i = tid; i < 4096; i += 256) {
            int m = i >> 5, k = i & 31;
            As[m][k] = A[(size_t)(m0 + m) * 64 + k0 + k];
        }
#pragma unroll
        for (int i = tid; i < 4096; i += 256) {
            int f = i >> 5, k = i & 31;
            BsT[k][f] = proj[(size_t)(n0 + f) * 64 + k0 + k];
        }
        __syncthreads();
#pragma unroll
        for (int k = 0; k < 32; k++) {
            float a[8], bb[8];
#pragma unroll
            for (int i = 0; i < 8; i++) a[i] = As[ty*8 + i][k];
            *(float4*)(bb)     = *(const float4*)&BsT[k][tx*8];
            *(float4*)(bb + 4) = *(const float4*)&BsT[k][tx*8 + 4];
#pragma unroll
            for (int i = 0; i < 8; i++)
#pragma unroll
                for (int j = 0; j < 8; j++) acc[i][j] += a[i] * bb[j];
        }
        __syncthreads();
    }
#pragma unroll
    for (int i = 0; i < 8; i++) {
        float v[8];
#pragma unroll
        for (int j = 0; j < 8; j++) v[j] = expf(acc[i][j]) + EPS;
        size_t row = (size_t)(m0 + ty*8 + i) * Ff + n0 + tx*8;
        *(float4*)&outp[row]     = *(float4*)(v);
        *(float4*)&outp[row + 4] = *(float4*)(v + 4);
    }
}

// ---------------- K3a: KV[b,h] += Kp^T @ V over a T-chunk (atomics) ----------------
__global__ __launch_bounds__(256) void k_kv() {
    int bh = blockIdx.z;            // 64
    int f0 = blockIdx.y * 128;      // 2 tiles over F
    int tc = blockIdx.x;            // 8 chunks of 512
    int b = bh >> 4, h = bh & 15;

    __shared__ float As[32][128];   // [t][f]
    __shared__ float Bs[32][64];    // [t][d]
    int tid = threadIdx.x;
    int tx = tid & 15, ty = tid >> 4;   // n = tx*4 (d), m = ty*8 (f)

    float acc[8][4];
#pragma unroll
    for (int i = 0; i < 8; i++)
#pragma unroll
        for (int j = 0; j < 4; j++) acc[i][j] = 0.f;

    int tbeg = tc * 512;
    for (int t0 = tbeg; t0 < tbeg + 512; t0 += 32) {
#pragma unroll
        for (int i = tid; i < 4096; i += 256) {
            int tk = i >> 7, f = i & 127;
            As[tk][f] = g_Kp[(size_t)(b*Tt + t0 + tk) * (Hh*Ff) + h*Ff + f0 + f];
        }
#pragma unroll
        for (int i = tid; i < 2048; i += 256) {
            int tk = i >> 6, d = i & 63;
            Bs[tk][d] = g_V[(size_t)(b*Tt + t0 + tk) * Ee + h*Dd + d];
        }
        __syncthreads();
#pragma unroll
        for (int k = 0; k < 32; k++) {
            float a[8];
            *(float4*)(a)     = *(const float4*)&As[k][ty*8];
            *(float4*)(a + 4) = *(const float4*)&As[k][ty*8 + 4];
            float4 bv = *(const float4*)&Bs[k][tx*4];
#pragma unroll
            for (int i = 0; i < 8; i++) {
                acc[i][0] += a[i] * bv.x;
                acc[i][1] += a[i] * bv.y;
                acc[i][2] += a[i] * bv.z;
                acc[i][3] += a[i] * bv.w;
            }
        }
        __syncthreads();
    }
#pragma unroll
    for (int i = 0; i < 8; i++)
#pragma unroll
        for (int j = 0; j < 4; j++)
            atomicAdd(&g_KV[(size_t)(bh*Ff + f0 + ty*8 + i) * Dd + tx*4 + j], acc[i][j]);
}

// ---------------- K3b: Ksum[b,h,f] += sum_t Kp ----------------
__global__ __launch_bounds__(256) void k_ksum() {
    int tc = blockIdx.x;     // 8 chunks of 512
    int bh = blockIdx.y;     // 64
    int b = bh >> 4, h = bh & 15;
    int f = threadIdx.x;
    float s = 0.f;
    int tbeg = tc * 512;
#pragma unroll 8
    for (int t = tbeg; t < tbeg + 512; t++)
        s += g_Kp[(size_t)(b*Tt + t) * (Hh*Ff) + h*Ff + f];
    atomicAdd(&g_Ksum[bh*Ff + f], s);
}

// ---------------- K4: attn = (Qp @ KV) / max(Qp . Ksum, 1e-6) ----------------
__global__ __launch_bounds__(256) void k_attn() {
    int tt = blockIdx.x;     // 32 tiles of 128 t
    int bh = blockIdx.y;     // 64
    int b = bh >> 4, h = bh & 15;
    int t0 = tt * 128;

    __shared__ float As[128][32];   // [m=t][k=f]
    __shared__ float Bs[32][64];    // [k=f][n=d]
    __shared__ float Ks[256];
    int tid = threadIdx.x;
    int tx = tid & 15, ty = tid >> 4;   // n = tx*4, m = ty*8

    Ks[tid] = g_Ksum[bh*Ff + tid];

    float acc[8][4], dacc[8];
#pragma unroll
    for (int i = 0; i < 8; i++) {
        dacc[i] = 0.f;
#pragma unroll
        for (int j = 0; j < 4; j++) acc[i][j] = 0.f;
    }

    for (int k0 = 0; k0 < Ff; k0 += 32) {
#pragma unroll
        for (int i = tid; i < 4096; i += 256) {
            int m = i >> 5, k = i & 31;
            As[m][k] = g_Qp[(size_t)(b*Tt + t0 + m) * (Hh*Ff) + h*Ff + k0 + k];
        }
#pragma unroll
        for (int i = tid; i < 2048; i += 256) {
            int k = i >> 6, d = i & 63;
            Bs[k][d] = g_KV[(size_t)(bh*Ff + k0 + k) * Dd + d];
        }
        __syncthreads();
#pragma unroll
        for (int k = 0; k < 32; k++) {
            float ks = Ks[k0 + k];
            float4 bv = *(const float4*)&Bs[k][tx*4];
            float a[8];
#pragma unroll
            for (int i = 0; i < 8; i++) a[i] = As[ty*8 + i][k];
#pragma unroll
            for (int i = 0; i < 8; i++) {
                dacc[i]  += a[i] * ks;
                acc[i][0] += a[i] * bv.x;
                acc[i][1] += a[i] * bv.y;
                acc[i][2] += a[i] * bv.z;
                acc[i][3] += a[i] * bv.w;
            }
        }
        __syncthreads();
    }
#pragma unroll
    for (int i = 0; i < 8; i++) {
        float inv = 1.0f / fmaxf(dacc[i], 1e-6f);
        float4 v = {acc[i][0]*inv, acc[i][1]*inv, acc[i][2]*inv, acc[i][3]*inv};
        *(float4*)&g_attn[(size_t)(b*Tt + t0 + ty*8 + i) * Ee + h*Dd + tx*4] = v;
    }
}

// ---------------- K5: out2 = attn @ Wo, stored transposed into out channels [512,1536) ----------------
__global__ __launch_bounds__(256) void k_out(const float* __restrict__ Wo,
                                             float* __restrict__ out) {
    int m0 = blockIdx.x * 128;   // over B*T
    int n0 = blockIdx.y * 128;   // over EMBED
    int b = m0 / Tt, t0 = m0 % Tt;

    __shared__ float As[128][16];   // [m][k]
    __shared__ float Bs[16][128];   // [k][n]
    int tid = threadIdx.x;
    int tx = tid & 15, ty = tid >> 4;

    float acc[8][8];
#pragma unroll
    for (int i = 0; i < 8; i++)
#pragma unroll
        for (int j = 0; j < 8; j++) acc[i][j] = 0.f;

    for (int k0 = 0; k0 < Ee; k0 += 16) {
#pragma unroll
        for (int i = tid; i < 2048; i += 256) {
            int m = i >> 4, k = i & 15;
            As[m][k] = g_attn[(size_t)(m0 + m) * Ee + k0 + k];
        }
#pragma unroll
        for (int i = tid; i < 2048; i += 256) {
            int k = i >> 7, n = i & 127;
            Bs[k][n] = Wo[(size_t)(k0 + k) * Ee + n0 + n];
        }
        __syncthreads();
#pragma unroll
        for (int k = 0; k < 16; k++) {
            float a[8], bb[8];
#pragma unroll
            for (int i = 0; i < 8; i++) a[i] = As[ty*8 + i][k];
            *(float4*)(bb)     = *(const float4*)&Bs[k][tx*8];
            *(float4*)(bb + 4) = *(const float4*)&Bs[k][tx*8 + 4];
#pragma unroll
            for (int i = 0; i < 8; i++)
#pragma unroll
                for (int j = 0; j < 8; j++) acc[i][j] += a[i] * bb[j];
        }
        __syncthreads();
    }
    // out[b][512 + n][t]; contiguous over t == contiguous over i -> float4 per (j, i-half)
#pragma unroll
    for (int j = 0; j < 8; j++) {
        size_t base = (size_t)b * CO * Tt + (size_t)(Cc + n0 + tx*8 + j) * Tt + t0 + ty*8;
        float4 v0 = {acc[0][j], acc[1][j], acc[2][j], acc[3][j]};
        float4 v1 = {acc[4][j], acc[5][j], acc[6][j], acc[7][j]};
        *(float4*)&out[base]     = v0;
        *(float4*)&out[base + 4] = v1;
    }
}

// ---------------- launch ----------------
extern "C" void kernel_launch(void* const* d_in, const int* in_sizes, int n_in,
                              void* d_out, int out_size) {
    const float* x    = (const float*)d_in[0];
    const float* Wq   = (const float*)d_in[1];
    const float* Wk   = (const float*)d_in[2];
    const float* Wv   = (const float*)d_in[3];
    const float* Wo   = (const float*)d_in[4];
    const float* proj = (const float*)d_in[5];
    float* out = (float*)d_out;

    k_zero<<<4096, 256>>>();
    k_copy<<<Bb*Cc*Tt/4/256, 256>>>(x, out);
    k_qkv<<<dim3(Bb*Tt/128, Ee/128, 3), 256>>>(x, Wq, Wk, Wv);
    k_feat<<<dim3(Bb*Tt*Hh/128, Ff/128, 2), 256>>>(proj);
    k_kv<<<dim3(8, 2, Bb*Hh), 256>>>();
    k_ksum<<<dim3(8, Bb*Hh), 256>>>();
    k_attn<<<dim3(Tt/128, Bb*Hh), 256>>>();
    k_out<<<dim3(Bb*Tt/128, Ee/128), 256>>>(Wo, out);
}

// round 3
// speedup vs baseline: 2.2998x; 2.2998x over previous
#include <cuda_runtime.h>
#include <cuda_bf16.h>
#include <cstdint>
#include <math.h>

// Problem constants
#define Bb 4
#define Cc 512      // IN_DIM
#define Tt 4096
#define Ee 1024     // EMBED
#define Hh 16
#define Dd 64
#define Ff 256
#define CO 1536     // output channels = Cc + Ee
#define EPS 1e-6f

// ---------------- scratch (device globals; no allocs allowed) ----------------
__device__ float g_V   [Bb*Tt*Ee];
__device__ float g_Qp  [Bb*Tt*Hh*Ff];
__device__ float g_Kp  [Bb*Tt*Hh*Ff];
__device__ float g_KV  [Bb*Hh*Ff*Dd];
__device__ float g_Ksum[Bb*Hh*Ff];

// bf16 split operands for tensor-core GEMMs
__device__ __align__(1024) __nv_bfloat16 g_xh[Bb*Tt*Cc];
__device__ __align__(1024) __nv_bfloat16 g_xl[Bb*Tt*Cc];
__device__ __align__(1024) __nv_bfloat16 g_Qh[Bb*Tt*Ee];
__device__ __align__(1024) __nv_bfloat16 g_Ql[Bb*Tt*Ee];
__device__ __align__(1024) __nv_bfloat16 g_Kh[Bb*Tt*Ee];
__device__ __align__(1024) __nv_bfloat16 g_Kl[Bb*Tt*Ee];
__device__ __align__(1024) __nv_bfloat16 g_Wqh[Ee*Cc], g_Wql[Ee*Cc];
__device__ __align__(1024) __nv_bfloat16 g_Wkh[Ee*Cc], g_Wkl[Ee*Cc];
__device__ __align__(1024) __nv_bfloat16 g_Wvh[Ee*Cc], g_Wvl[Ee*Cc];
__device__ __align__(1024) __nv_bfloat16 g_Woh[Ee*Ee], g_Wol[Ee*Ee];
__device__ __align__(1024) __nv_bfloat16 g_ph[Ff*Dd],  g_pl[Ff*Dd];
__device__ __align__(1024) __nv_bfloat16 g_ah[Bb*Tt*Ee], g_al[Bb*Tt*Ee];

// ================= PTX helpers (base sm_80+ features only) =================
__device__ __forceinline__ uint32_t s2u(const void* p){
    uint32_t a;
    asm("{ .reg .u64 t; cvta.to.shared.u64 t, %1; cvt.u32.u64 %0, t; }" : "=r"(a) : "l"(p));
    return a;
}
__device__ __forceinline__ uint32_t swz(uint32_t off){ return off ^ ((off >> 3) & 0x70); }

__device__ __forceinline__ void ldsm4(uint32_t& r0, uint32_t& r1, uint32_t& r2, uint32_t& r3, uint32_t addr){
    asm volatile("ldmatrix.sync.aligned.m8n8.x4.shared.b16 {%0,%1,%2,%3}, [%4];"
        : "=r"(r0), "=r"(r1), "=r"(r2), "=r"(r3) : "r"(addr));
}
__device__ __forceinline__ void mma_bf16(float* c, const uint32_t* a, const uint32_t* b){
    asm volatile("mma.sync.aligned.m16n8k16.row.col.f32.bf16.bf16.f32 "
        "{%0,%1,%2,%3}, {%4,%5,%6,%7}, {%8,%9}, {%0,%1,%2,%3};"
        : "+f"(c[0]), "+f"(c[1]), "+f"(c[2]), "+f"(c[3])
        : "r"(a[0]), "r"(a[1]), "r"(a[2]), "r"(a[3]), "r"(b[0]), "r"(b[1]));
}
__device__ __forceinline__ void cpa16(uint32_t s, const void* g){
    asm volatile("cp.async.cg.shared.global [%0], [%1], 16;" :: "r"(s), "l"(g));
}
__device__ __forceinline__ void cpa_commit(){ asm volatile("cp.async.commit_group;" ::: "memory"); }
__device__ __forceinline__ void cpa_wait0(){ asm volatile("cp.async.wait_group 0;" ::: "memory"); }
__device__ __forceinline__ void cpa_wait1(){ asm volatile("cp.async.wait_group 1;" ::: "memory"); }

__device__ __forceinline__ void split2(float a, __nv_bfloat16& h, __nv_bfloat16& l){
    h = __float2bfloat16(a);
    l = __float2bfloat16(a - __bfloat162float(h));
}

// ================= small kernels =================
__global__ void k_zero() {
    int i = blockIdx.x * 256 + threadIdx.x;
    if (i < Bb*Hh*Ff*Dd) g_KV[i] = 0.f;
    if (i < Bb*Hh*Ff)    g_Ksum[i] = 0.f;
}

__global__ void k_copy(const float* __restrict__ x, float* __restrict__ out) {
    int i = blockIdx.x * 256 + threadIdx.x;
    const int per_b = Cc * Tt / 4;
    int b = i / per_b, r = i % per_b;
    const float4* x4 = (const float4*)x;
    float4* o4 = (float4*)out;
    o4[(size_t)b * (CO*Tt/4) + r] = x4[(size_t)b * per_b + r];
}

// x (B,C,T) -> xh/xl [b*T+t][c]
__global__ void k_prep_x(const float* __restrict__ x){
    __shared__ float tile[32][33];
    int b = blockIdx.z;
    int t0 = blockIdx.x*32, c0 = blockIdx.y*32;
    int tx = threadIdx.x, ty = threadIdx.y;
    for (int i = ty; i < 32; i += 8)
        tile[i][tx] = x[((size_t)b*Cc + c0 + i)*Tt + t0 + tx];
    __syncthreads();
    for (int i = ty; i < 32; i += 8){
        float v = tile[tx][i];
        __nv_bfloat16 hi, lo; split2(v, hi, lo);
        size_t o = ((size_t)b*Tt + t0 + i)*Cc + c0 + tx;
        g_xh[o] = hi; g_xl[o] = lo;
    }
}

// W [Kd][Nd=Ee] -> W^T hi/lo [Nd][Kd]
__global__ void k_prep_w(const float* __restrict__ W, int widx, int Kd){
    const int Nd = Ee;
    __nv_bfloat16 *Dh, *Dl;
    if      (widx == 0){ Dh = g_Wqh; Dl = g_Wql; }
    else if (widx == 1){ Dh = g_Wkh; Dl = g_Wkl; }
    else if (widx == 2){ Dh = g_Wvh; Dl = g_Wvl; }
    else               { Dh = g_Woh; Dl = g_Wol; }
    __shared__ float tile[32][33];
    int n0 = blockIdx.x*32, k0 = blockIdx.y*32;
    int tx = threadIdx.x, ty = threadIdx.y;
    for (int i = ty; i < 32; i += 8)
        tile[i][tx] = W[(size_t)(k0 + i)*Nd + n0 + tx];
    __syncthreads();
    for (int i = ty; i < 32; i += 8){
        float v = tile[tx][i];
        __nv_bfloat16 hi, lo; split2(v, hi, lo);
        size_t o = (size_t)(n0 + i)*Kd + k0 + tx;
        Dh[o] = hi; Dl[o] = lo;
    }
}

// proj [F][D] already [n][k]: elementwise split
__global__ void k_prep_proj(const float* __restrict__ proj){
    int i = blockIdx.x * 256 + threadIdx.x;
    if (i < Ff*Dd){
        __nv_bfloat16 hi, lo; split2(proj[i], hi, lo);
        g_ph[i] = hi; g_pl[i] = lo;
    }
}

// ================= unified split-bf16 mma.sync GEMM =================
// C[128x128] = A[m][K] @ B[n][K]^T, A/B as hi/lo bf16 pairs, fp32 accum, 3-MMA compensation.
// mode 0: QKV   (z: 0=Q,1=K -> split bf16 out; 2=V -> fp32)
// mode 1: Wo    -> transposed store into out[b][Cc+n][t]
// mode 2: feat  (z: 0=Qp, 1=Kp) -> exp(acc)+eps, fp32 [m][256]
#define STAGE_BYTES 65536   // Ah 16K | Al 16K | Bh 16K | Bl 16K
#define DSM_BYTES   131072

__device__ __forceinline__ void load_tile(uint32_t sbase, const __nv_bfloat16* g,
                                          int row0, int K, int k0, int tid){
#pragma unroll
    for (int i = 0; i < 4; i++){
        int idx = tid + i*256;
        int r = idx >> 3, kc = idx & 7;
        uint32_t off = (uint32_t)(r*128 + kc*16);
        cpa16(sbase + swz(off), g + (size_t)(row0 + r)*K + k0 + kc*8);
    }
}
__device__ __forceinline__ void load_stage(uint32_t st, const __nv_bfloat16* Ah, const __nv_bfloat16* Al,
                                           const __nv_bfloat16* Bh, const __nv_bfloat16* Bl,
                                           int m0, int n0, int K, int k0, int tid){
    load_tile(st,         Ah, m0, K, k0, tid);
    load_tile(st + 16384, Al, m0, K, k0, tid);
    load_tile(st + 32768, Bh, n0, K, k0, tid);
    load_tile(st + 49152, Bl, n0, K, k0, tid);
    cpa_commit();
}

__global__ __launch_bounds__(256, 1) void k_mma(int K, int mode, float* __restrict__ outp){
    extern __shared__ __align__(1024) char dsm[];
    uint32_t sb = s2u(dsm);
    int tid = threadIdx.x;
    int lane = tid & 31, w = tid >> 5;
    int z = blockIdx.z;
    int m0 = blockIdx.x * 128, n0 = blockIdx.y * 128;

    const __nv_bfloat16 *Ah, *Al, *Bh, *Bl;
    if (mode == 0){
        Ah = g_xh; Al = g_xl;
        Bh = (z == 0) ? g_Wqh : (z == 1) ? g_Wkh : g_Wvh;
        Bl = (z == 0) ? g_Wql : (z == 1) ? g_Wkl : g_Wvl;
    } else if (mode == 1){
        Ah = g_ah; Al = g_al; Bh = g_Woh; Bl = g_Wol;
    } else {
        Ah = z ? g_Kh : g_Qh; Al = z ? g_Kl : g_Ql;
        Bh = g_ph; Bl = g_pl;
    }

    float acc[4][4][4];
#pragma unroll
    for (int i = 0; i < 4; i++)
#pragma unroll
        for (int j = 0; j < 4; j++)
#pragma unroll
            for (int c = 0; c < 4; c++) acc[i][j][c] = 0.f;

    const int NKT = K >> 6;
    load_stage(sb, Ah, Al, Bh, Bl, m0, n0, K, 0, tid);
    if (NKT > 1) load_stage(sb + STAGE_BYTES, Ah, Al, Bh, Bl, m0, n0, K, 64, tid);

    // per-lane ldmatrix geometry
    int rr = lane & 7, sub = lane >> 3;
    int wm = (w & 1) * 64, wn = (w >> 1) * 32;
    int arow = wm + rr + (sub & 1) * 8;
    int acb0 = (sub >> 1) * 16;
    int brow = wn + rr + (sub >> 1) * 8;
    int bcb0 = (sub & 1) * 16;

    for (int kt = 0; kt < NKT; kt++){
        uint32_t st = sb + (uint32_t)(kt & 1) * STAGE_BYTES;
        if (kt + 1 < NKT) cpa_wait1(); else cpa_wait0();
        __syncthreads();
#pragma unroll
        for (int ks = 0; ks < 4; ks++){
            uint32_t ahf[4][4], alf[4][4], bhf[4][2], blf[4][2];
#pragma unroll
            for (int i = 0; i < 4; i++){
                uint32_t sa = swz((uint32_t)((arow + i*16)*128 + acb0 + ks*32));
                ldsm4(ahf[i][0], ahf[i][1], ahf[i][2], ahf[i][3], st + sa);
                ldsm4(alf[i][0], alf[i][1], alf[i][2], alf[i][3], st + 16384 + sa);
            }
#pragma unroll
            for (int j2 = 0; j2 < 2; j2++){
                uint32_t sa = swz((uint32_t)((brow + j2*16)*128 + bcb0 + ks*32));
                uint32_t r0, r1, r2, r3;
                ldsm4(r0, r1, r2, r3, st + 32768 + sa);
                bhf[j2*2][0] = r0; bhf[j2*2][1] = r1; bhf[j2*2+1][0] = r2; bhf[j2*2+1][1] = r3;
                ldsm4(r0, r1, r2, r3, st + 49152 + sa);
                blf[j2*2][0] = r0; blf[j2*2][1] = r1; blf[j2*2+1][0] = r2; blf[j2*2+1][1] = r3;
            }
#pragma unroll
            for (int i = 0; i < 4; i++)
#pragma unroll
                for (int j = 0; j < 4; j++){
                    mma_bf16(acc[i][j], ahf[i], bhf[j]);
                    mma_bf16(acc[i][j], ahf[i], blf[j]);
                    mma_bf16(acc[i][j], alf[i], bhf[j]);
                }
        }
        __syncthreads();
        if (kt + 2 < NKT)
            load_stage(sb + (uint32_t)(kt & 1)*STAGE_BYTES, Ah, Al, Bh, Bl, m0, n0, K, (kt + 2)*64, tid);
    }

    // ---------------- epilogues ----------------
    int r0row = lane >> 2, c0 = (lane & 3) * 2;
    if (mode == 0){
        if (z < 2){
            __nv_bfloat16* Dh = z ? g_Kh : g_Qh;
            __nv_bfloat16* Dl = z ? g_Kl : g_Ql;
#pragma unroll
            for (int i = 0; i < 4; i++)
#pragma unroll
                for (int j = 0; j < 4; j++)
#pragma unroll
                    for (int half = 0; half < 2; half++){
                        int row = m0 + wm + i*16 + r0row + half*8;
                        int col = n0 + wn + j*8 + c0;
                        float v0 = acc[i][j][half*2], v1 = acc[i][j][half*2 + 1];
                        __nv_bfloat16 h0, l0, h1, l1;
                        split2(v0, h0, l0); split2(v1, h1, l1);
                        *(__nv_bfloat162*)&Dh[(size_t)row*Ee + col] = __nv_bfloat162{h0, h1};
                        *(__nv_bfloat162*)&Dl[(size_t)row*Ee + col] = __nv_bfloat162{l0, l1};
                    }
        } else {
#pragma unroll
            for (int i = 0; i < 4; i++)
#pragma unroll
                for (int j = 0; j < 4; j++)
#pragma unroll
                    for (int half = 0; half < 2; half++){
                        int row = m0 + wm + i*16 + r0row + half*8;
                        int col = n0 + wn + j*8 + c0;
                        float2 v = {acc[i][j][half*2], acc[i][j][half*2 + 1]};
                        *(float2*)&g_V[(size_t)row*Ee + col] = v;
                    }
        }
    } else if (mode == 2){
        float* O = z ? g_Kp : g_Qp;
#pragma unroll
        for (int i = 0; i < 4; i++)
#pragma unroll
            for (int j = 0; j < 4; j++)
#pragma unroll
                for (int half = 0; half < 2; half++){
                    int row = m0 + wm + i*16 + r0row + half*8;
                    int col = n0 + wn + j*8 + c0;
                    float2 v = {expf(acc[i][j][half*2]) + EPS, expf(acc[i][j][half*2 + 1]) + EPS};
                    *(float2*)&O[(size_t)row*Ff + col] = v;
                }
    } else {
        // mode 1: smem transpose, then coalesced transposed store into out[b][Cc+n][t]
        float* fb = (float*)dsm;   // 128 x 129 fp32
#pragma unroll
        for (int i = 0; i < 4; i++)
#pragma unroll
            for (int j = 0; j < 4; j++)
#pragma unroll
                for (int half = 0; half < 2; half++){
                    int row = wm + i*16 + r0row + half*8;
                    int col = wn + j*8 + c0;
                    fb[row*129 + col]     = acc[i][j][half*2];
                    fb[row*129 + col + 1] = acc[i][j][half*2 + 1];
                }
        __syncthreads();
        int b = m0 / Tt, t0 = m0 % Tt;
        for (int idx = tid; idx < 16384; idx += 256){
            int n = idx >> 7, t = idx & 127;
            outp[(size_t)b*CO*Tt + (size_t)(Cc + n0 + n)*Tt + t0 + t] = fb[t*129 + n];
        }
    }
}

// ================= K3a: KV += Kp^T @ V (chunked, atomics) =================
__global__ __launch_bounds__(256) void k_kv() {
    int bh = blockIdx.z;
    int f0 = blockIdx.y * 128;
    int tc = blockIdx.x;
    int b = bh >> 4, h = bh & 15;

    __shared__ float As[32][128];
    __shared__ float Bs[32][64];
    int tid = threadIdx.x;
    int tx = tid & 15, ty = tid >> 4;

    float acc[8][4];
#pragma unroll
    for (int i = 0; i < 8; i++)
#pragma unroll
        for (int j = 0; j < 4; j++) acc[i][j] = 0.f;

    int tbeg = tc * 512;
    for (int t0 = tbeg; t0 < tbeg + 512; t0 += 32) {
#pragma unroll
        for (int i = tid; i < 4096; i += 256) {
            int tk = i >> 7, f = i & 127;
            As[tk][f] = g_Kp[(size_t)(b*Tt + t0 + tk) * (Hh*Ff) + h*Ff + f0 + f];
        }
#pragma unroll
        for (int i = tid; i < 2048; i += 256) {
            int tk = i >> 6, d = i & 63;
            Bs[tk][d] = g_V[(size_t)(b*Tt + t0 + tk) * Ee + h*Dd + d];
        }
        __syncthreads();
#pragma unroll
        for (int k = 0; k < 32; k++) {
            float a[8];
            *(float4*)(a)     = *(const float4*)&As[k][ty*8];
            *(float4*)(a + 4) = *(const float4*)&As[k][ty*8 + 4];
            float4 bv = *(const float4*)&Bs[k][tx*4];
#pragma unroll
            for (int i = 0; i < 8; i++) {
                acc[i][0] += a[i] * bv.x;
                acc[i][1] += a[i] * bv.y;
                acc[i][2] += a[i] * bv.z;
                acc[i][3] += a[i] * bv.w;
            }
        }
        __syncthreads();
    }
#pragma unroll
    for (int i = 0; i < 8; i++)
#pragma unroll
        for (int j = 0; j < 4; j++)
            atomicAdd(&g_KV[(size_t)(bh*Ff + f0 + ty*8 + i) * Dd + tx*4 + j], acc[i][j]);
}

// ================= K3b: Ksum =================
__global__ __launch_bounds__(256) void k_ksum() {
    int tc = blockIdx.x;
    int bh = blockIdx.y;
    int b = bh >> 4, h = bh & 15;
    int f = threadIdx.x;
    float s = 0.f;
    int tbeg = tc * 512;
#pragma unroll 8
    for (int t = tbeg; t < tbeg + 512; t++)
        s += g_Kp[(size_t)(b*Tt + t) * (Hh*Ff) + h*Ff + f];
    atomicAdd(&g_Ksum[bh*Ff + f], s);
}

// ================= K4: attn = (Qp @ KV) / max(Qp . Ksum, 1e-6) -> hi/lo bf16 =================
__global__ __launch_bounds__(256) void k_attn() {
    int tt = blockIdx.x;
    int bh = blockIdx.y;
    int b = bh >> 4, hd = bh & 15;
    int t0 = tt * 128;

    __shared__ float As[128][32];
    __shared__ float Bs[32][64];
    __shared__ float Ks[256];
    int tid = threadIdx.x;
    int tx = tid & 15, ty = tid >> 4;

    Ks[tid] = g_Ksum[bh*Ff + tid];

    float acc[8][4], dacc[8];
#pragma unroll
    for (int i = 0; i < 8; i++) {
        dacc[i] = 0.f;
#pragma unroll
        for (int j = 0; j < 4; j++) acc[i][j] = 0.f;
    }

    for (int k0 = 0; k0 < Ff; k0 += 32) {
#pragma unroll
        for (int i = tid; i < 4096; i += 256) {
            int m = i >> 5, k = i & 31;
            As[m][k] = g_Qp[(size_t)(b*Tt + t0 + m) * (Hh*Ff) + hd*Ff + k0 + k];
        }
#pragma unroll
        for (int i = tid; i < 2048; i += 256) {
            int k = i >> 6, d = i & 63;
            Bs[k][d] = g_KV[(size_t)(bh*Ff + k0 + k) * Dd + d];
        }
        __syncthreads();
#pragma unroll
        for (int k = 0; k < 32; k++) {
            float ks = Ks[k0 + k];
            float4 bv = *(const float4*)&Bs[k][tx*4];
            float a[8];
#pragma unroll
            for (int i = 0; i < 8; i++) a[i] = As[ty*8 + i][k];
#pragma unroll
            for (int i = 0; i < 8; i++) {
                dacc[i]  += a[i] * ks;
                acc[i][0] += a[i] * bv.x;
                acc[i][1] += a[i] * bv.y;
                acc[i][2] += a[i] * bv.z;
                acc[i][3] += a[i] * bv.w;
            }
        }
        __syncthreads();
    }
#pragma unroll
    for (int i = 0; i < 8; i++) {
        float inv = 1.0f / fmaxf(dacc[i], 1e-6f);
        size_t base = (size_t)(b*Tt + t0 + ty*8 + i) * Ee + hd*Dd + tx*4;
#pragma unroll
        for (int j = 0; j < 4; j++) {
            float v = acc[i][j] * inv;
            __nv_bfloat16 hi, lo; split2(v, hi, lo);
            g_ah[base + j] = hi;
            g_al[base + j] = lo;
        }
    }
}

// ================= launch =================
extern "C" void kernel_launch(void* const* d_in, const int* in_sizes, int n_in,
                              void* d_out, int out_size) {
    const float* x    = (const float*)d_in[0];
    const float* Wq   = (const float*)d_in[1];
    const float* Wk   = (const float*)d_in[2];
    const float* Wv   = (const float*)d_in[3];
    const float* Wo   = (const float*)d_in[4];
    const float* proj = (const float*)d_in[5];
    float* out = (float*)d_out;

    cudaFuncSetAttribute(k_mma, cudaFuncAttributeMaxDynamicSharedMemorySize, DSM_BYTES);

    k_zero<<<4096, 256>>>();
    k_copy<<<Bb*Cc*Tt/4/256, 256>>>(x, out);
    k_prep_x<<<dim3(Tt/32, Cc/32, Bb), dim3(32, 8)>>>(x);
    k_prep_w<<<dim3(Ee/32, Cc/32), dim3(32, 8)>>>(Wq, 0, Cc);
    k_prep_w<<<dim3(Ee/32, Cc/32), dim3(32, 8)>>>(Wk, 1, Cc);
    k_prep_w<<<dim3(Ee/32, Cc/32), dim3(32, 8)>>>(Wv, 2, Cc);
    k_prep_w<<<dim3(Ee/32, Ee/32), dim3(32, 8)>>>(Wo, 3, Ee);
    k_prep_proj<<<(Ff*Dd + 255)/256, 256>>>(proj);

    // Q,K (split bf16 out) + V (fp32): M=16384, N=1024, K=512
    k_mma<<<dim3(Bb*Tt/128, Ee/128, 3), 256, DSM_BYTES>>>(Cc, 0, nullptr);
    // Qp/Kp = exp(Q @ proj^T)+eps: M=262144, N=256, K=64
    k_mma<<<dim3(Bb*Tt*Hh/128, Ff/128, 2), 256, DSM_BYTES>>>(Dd, 2, nullptr);

    k_kv<<<dim3(8, 2, Bb*Hh), 256>>>();
    k_ksum<<<dim3(8, Bb*Hh), 256>>>();
    k_attn<<<dim3(Tt/128, Bb*Hh), 256>>>();

    // out2 = attn @ Wo, transposed store + concat: M=16384, N=1024, K=1024
    k_mma<<<dim3(Bb*Tt/128, Ee/128, 1), 256, DSM_BYTES>>>(Ee, 1, out);
}

// round 4
// speedup vs baseline: 2.7307x; 1.1874x over previous
#include <cuda_runtime.h>
#include <cuda_bf16.h>
#include <cstdint>
#include <math.h>

// Problem constants
#define Bb 4
#define Cc 512      // IN_DIM
#define Tt 4096
#define Ee 1024     // EMBED
#define Hh 16
#define Dd 64
#define Ff 256
#define CO 1536     // output channels = Cc + Ee
#define EPS 1e-6f

// ---------------- scratch (device globals; no allocs allowed) ----------------
// split-bf16 operands
__device__ __align__(1024) __nv_bfloat16 g_xh[Bb*Tt*Cc],  g_xl[Bb*Tt*Cc];     // x^T [bt][c]
__device__ __align__(1024) __nv_bfloat16 g_Qh[Bb*Tt*Ee],  g_Ql[Bb*Tt*Ee];     // Q [bt][e]
__device__ __align__(1024) __nv_bfloat16 g_Kh[Bb*Tt*Ee],  g_Kl[Bb*Tt*Ee];     // K [bt][e]
__device__ __align__(1024) __nv_bfloat16 g_Vth[Bb*Ee*Tt], g_Vtl[Bb*Ee*Tt];    // V^T [b][e][t]
__device__ __align__(1024) __nv_bfloat16 g_Wqh[Ee*Cc],    g_Wql[Ee*Cc];       // W^T [n][k]
__device__ __align__(1024) __nv_bfloat16 g_Wkh[Ee*Cc],    g_Wkl[Ee*Cc];
__device__ __align__(1024) __nv_bfloat16 g_Wvh[Ee*Cc],    g_Wvl[Ee*Cc];
__device__ __align__(1024) __nv_bfloat16 g_Woh[Ee*Ee],    g_Wol[Ee*Ee];
__device__ __align__(1024) __nv_bfloat16 g_ph[Ff*Dd],     g_pl[Ff*Dd];        // proj [f][d]
__device__ __align__(1024) __nv_bfloat16 g_Qph[Bb*Hh*Tt*Ff], g_Qpl[Bb*Hh*Tt*Ff];  // Qp [bh][t][f]
__device__ __align__(1024) __nv_bfloat16 g_Kpth[Bb*Hh*Ff*Tt], g_Kptl[Bb*Hh*Ff*Tt]; // Kp^T [bh][f][t]
__device__ __align__(1024) __nv_bfloat16 g_ah[Bb*Tt*Ee],  g_al[Bb*Tt*Ee];     // attn [bt][e]
__device__ __align__(1024) __nv_bfloat16 g_KVth[Bb*Hh*128*Ff], g_KVtl[Bb*Hh*128*Ff]; // KV^T+Ksum [bh][n][f]
__device__ __align__(1024) __nv_bfloat16 g_onesh[Tt];
__device__ float g_KVt[Bb*Hh*128*Ff];   // fp32 accumulation target, row n=64 is Ksum

// ================= PTX helpers (base sm_80+ features only) =================
__device__ __forceinline__ uint32_t s2u(const void* p){
    uint32_t a;
    asm("{ .reg .u64 t; cvta.to.shared.u64 t, %1; cvt.u32.u64 %0, t; }" : "=r"(a) : "l"(p));
    return a;
}
__device__ __forceinline__ uint32_t swz(uint32_t off){ return off ^ ((off >> 3) & 0x70); }

__device__ __forceinline__ void ldsm4(uint32_t& r0, uint32_t& r1, uint32_t& r2, uint32_t& r3, uint32_t addr){
    asm volatile("ldmatrix.sync.aligned.m8n8.x4.shared.b16 {%0,%1,%2,%3}, [%4];"
        : "=r"(r0), "=r"(r1), "=r"(r2), "=r"(r3) : "r"(addr));
}
__device__ __forceinline__ void mma_bf16(float* c, const uint32_t* a, const uint32_t* b){
    asm volatile("mma.sync.aligned.m16n8k16.row.col.f32.bf16.bf16.f32 "
        "{%0,%1,%2,%3}, {%4,%5,%6,%7}, {%8,%9}, {%0,%1,%2,%3};"
        : "+f"(c[0]), "+f"(c[1]), "+f"(c[2]), "+f"(c[3])
        : "r"(a[0]), "r"(a[1]), "r"(a[2]), "r"(a[3]), "r"(b[0]), "r"(b[1]));
}
__device__ __forceinline__ void cpa16(uint32_t s, const void* g){
    asm volatile("cp.async.cg.shared.global [%0], [%1], 16;" :: "r"(s), "l"(g));
}
__device__ __forceinline__ void cpa_commit(){ asm volatile("cp.async.commit_group;" ::: "memory"); }
__device__ __forceinline__ void cpa_wait0(){ asm volatile("cp.async.wait_group 0;" ::: "memory"); }
__device__ __forceinline__ void cpa_wait1(){ asm volatile("cp.async.wait_group 1;" ::: "memory"); }

__device__ __forceinline__ void split2(float a, __nv_bfloat16& h, __nv_bfloat16& l){
    h = __float2bfloat16(a);
    l = __float2bfloat16(a - __bfloat162float(h));
}

// ================= small kernels =================
__global__ void k_zero() {
    int i = blockIdx.x * 256 + threadIdx.x;
    if (i < Bb*Hh*128*Ff) g_KVt[i] = 0.f;
}

__global__ void k_copy(const float* __restrict__ x, float* __restrict__ out) {
    int i = blockIdx.x * 256 + threadIdx.x;
    const int per_b = Cc * Tt / 4;
    int b = i / per_b, r = i % per_b;
    const float4* x4 = (const float4*)x;
    float4* o4 = (float4*)out;
    o4[(size_t)b * (CO*Tt/4) + r] = x4[(size_t)b * per_b + r];
}

// x (B,C,T) -> xh/xl [b*T+t][c]
__global__ void k_prep_x(const float* __restrict__ x){
    __shared__ float tile[32][33];
    int b = blockIdx.z;
    int t0 = blockIdx.x*32, c0 = blockIdx.y*32;
    int tx = threadIdx.x, ty = threadIdx.y;
    for (int i = ty; i < 32; i += 8)
        tile[i][tx] = x[((size_t)b*Cc + c0 + i)*Tt + t0 + tx];
    __syncthreads();
    for (int i = ty; i < 32; i += 8){
        float v = tile[tx][i];
        __nv_bfloat16 hi, lo; split2(v, hi, lo);
        size_t o = ((size_t)b*Tt + t0 + i)*Cc + c0 + tx;
        g_xh[o] = hi; g_xl[o] = lo;
    }
}

// W [Kd][Nd=Ee] -> W^T hi/lo [Nd][Kd]
__global__ void k_prep_w(const float* __restrict__ W, int widx, int Kd){
    const int Nd = Ee;
    __nv_bfloat16 *Dh, *Dl;
    if      (widx == 0){ Dh = g_Wqh; Dl = g_Wql; }
    else if (widx == 1){ Dh = g_Wkh; Dl = g_Wkl; }
    else if (widx == 2){ Dh = g_Wvh; Dl = g_Wvl; }
    else               { Dh = g_Woh; Dl = g_Wol; }
    __shared__ float tile[32][33];
    int n0 = blockIdx.x*32, k0 = blockIdx.y*32;
    int tx = threadIdx.x, ty = threadIdx.y;
    for (int i = ty; i < 32; i += 8)
        tile[i][tx] = W[(size_t)(k0 + i)*Nd + n0 + tx];
    __syncthreads();
    for (int i = ty; i < 32; i += 8){
        float v = tile[tx][i];
        __nv_bfloat16 hi, lo; split2(v, hi, lo);
        size_t o = (size_t)(n0 + i)*Kd + k0 + tx;
        Dh[o] = hi; Dl[o] = lo;
    }
}

__global__ void k_prep_proj(const float* __restrict__ proj){
    int i = blockIdx.x * 256 + threadIdx.x;
    if (i < Ff*Dd){
        __nv_bfloat16 hi, lo; split2(proj[i], hi, lo);
        g_ph[i] = hi; g_pl[i] = lo;
    }
}

__global__ void k_prep_ones(){
    int i = blockIdx.x * 256 + threadIdx.x;
    if (i < Tt) g_onesh[i] = __float2bfloat16(1.0f);
}

__global__ void k_cvt_kv(){
    int i = blockIdx.x * 256 + threadIdx.x;
    if (i < Bb*Hh*128*Ff){
        __nv_bfloat16 h, l; split2(g_KVt[i], h, l);
        g_KVth[i] = h; g_KVtl[i] = l;
    }
}

// ================= unified split-bf16 mma.sync GEMM =================
// Block tile 128(m) x 128(n), k-tiles of 64, 8 warps, fp32 accum, 3-MMA split compensation.
// mode 0: QKV  (z: 0=Q split out, 1=K split out, 2=V -> transposed split out)
// mode 1: Wo   -> transposed fp32 store into out[b][Cc+n][t]
// mode 2: feat (z&1: 0=Qp direct split, 1=Kp transposed split), bh = z>>1
// mode 3: kv   C[f][n] = Kp^T @ [V^T|1|0..], atomicAdd transposed into g_KVt
// mode 4: attn numer/denom -> g_ah/g_al
#define STAGE_BYTES 65536   // Ah 16K | Al 16K | Bh 16K | Bl 16K
#define DSM_BYTES   131072

__device__ __forceinline__ void load_tile(uint32_t sbase, const __nv_bfloat16* g,
                                          int row0, int stride, int k0, int tid){
#pragma unroll
    for (int i = 0; i < 4; i++){
        int idx = tid + i*256;
        int r = idx >> 3, kc = idx & 7;
        cpa16(sbase + swz((uint32_t)(r*128 + kc*16)), g + (size_t)(row0 + r)*stride + k0 + kc*8);
    }
}

__device__ __forceinline__ void load_stageM(uint32_t st,
    const __nv_bfloat16* Ahp, const __nv_bfloat16* Alp,
    const __nv_bfloat16* Bhp, const __nv_bfloat16* Blp,
    int rowA0, int strideA, int rowB0, int strideB, int k0, bool kvB, int tid){
    load_tile(st,         Ahp, rowA0, strideA, k0, tid);
    load_tile(st + 16384, Alp, rowA0, strideA, k0, tid);
    if (!kvB){
        load_tile(st + 32768, Bhp, rowB0, strideB, k0, tid);
        load_tile(st + 49152, Blp, rowB0, strideB, k0, tid);
    } else {
        // rows 0-63: V^T; row 64: ones; rows 65-127 pre-zeroed
        for (int idx = tid; idx < 520; idx += 256){
            int r = idx >> 3, kc = idx & 7;
            const __nv_bfloat16* src = (r < 64) ? Bhp + (size_t)(rowB0 + r)*strideB + k0 + kc*8
                                                : g_onesh + k0 + kc*8;
            cpa16(st + 32768 + swz((uint32_t)(r*128 + kc*16)), src);
        }
        for (int idx = tid; idx < 512; idx += 256){
            int r = idx >> 3, kc = idx & 7;
            cpa16(st + 49152 + swz((uint32_t)(r*128 + kc*16)),
                  Blp + (size_t)(rowB0 + r)*strideB + k0 + kc*8);
        }
    }
    cpa_commit();
}

__global__ __launch_bounds__(256, 1) void k_mma(int mode, float* __restrict__ outp){
    extern __shared__ __align__(1024) char dsm[];
    __shared__ float sden[128];
    uint32_t sb = s2u(dsm);
    int tid = threadIdx.x;
    int lane = tid & 31, w = tid >> 5;
    int bz = blockIdx.z;
    int m0 = blockIdx.x * 128, n0 = blockIdx.y * 128;

    const __nv_bfloat16 *Ahp, *Alp, *Bhp, *Blp;
    int rowA0, rowB0, strideA, strideB, NKT, k0base = 0;
    bool kvB = false;
    int bh = 0;

    if (mode == 0){
        Ahp = g_xh; Alp = g_xl;
        Bhp = bz == 0 ? g_Wqh : bz == 1 ? g_Wkh : g_Wvh;
        Blp = bz == 0 ? g_Wql : bz == 1 ? g_Wkl : g_Wvl;
        rowA0 = m0; strideA = Cc; rowB0 = n0; strideB = Cc; NKT = 8;
    } else if (mode == 1){
        Ahp = g_ah; Alp = g_al; Bhp = g_Woh; Blp = g_Wol;
        rowA0 = m0; strideA = Ee; rowB0 = n0; strideB = Ee; NKT = 16;
    } else if (mode == 2){
        int qk = bz & 1; bh = bz >> 1;
        Ahp = (qk ? g_Kh : g_Qh) + (bh & 15)*Dd;
        Alp = (qk ? g_Kl : g_Ql) + (bh & 15)*Dd;
        rowA0 = (bh >> 4)*Tt + m0;      // m0 = t0
        strideA = Ee;
        Bhp = g_ph; Blp = g_pl; rowB0 = n0; strideB = Dd; NKT = 1;
    } else if (mode == 3){
        bh = bz;
        Ahp = g_Kpth; Alp = g_Kptl;
        rowA0 = bh*Ff + m0; strideA = Tt;   // m0 = f-tile
        Bhp = g_Vth; Blp = g_Vtl;
        rowB0 = (bh >> 4)*Ee + (bh & 15)*Dd; strideB = Tt;
        k0base = blockIdx.y * 2048; NKT = 32; kvB = true;
    } else {
        bh = bz;
        Ahp = g_Qph; Alp = g_Qpl;
        rowA0 = bh*Tt + m0; strideA = Ff;   // m0 = t0
        Bhp = g_KVth; Blp = g_KVtl;
        rowB0 = bh*128; strideB = Ff; NKT = 4;
    }

    // pre-zero padding rows of B tiles for kv mode (stay zero across k-loop)
    if (kvB){
        uint4 z4 = {0,0,0,0};
#pragma unroll
        for (int s = 0; s < 2; s++){
            char* base = dsm + s*STAGE_BYTES;
            for (int i = tid*16; i < 8064; i += 4096) *(uint4*)(base + 32768 + 8320 + i) = z4;
            for (int i = tid*16; i < 8192; i += 4096) *(uint4*)(base + 49152 + 8192 + i) = z4;
        }
    }

    float acc[4][4][4];
#pragma unroll
    for (int i = 0; i < 4; i++)
#pragma unroll
        for (int j = 0; j < 4; j++)
#pragma unroll
            for (int c = 0; c < 4; c++) acc[i][j][c] = 0.f;

    load_stageM(sb, Ahp, Alp, Bhp, Blp, rowA0, strideA, rowB0, strideB, k0base, kvB, tid);
    if (NKT > 1)
        load_stageM(sb + STAGE_BYTES, Ahp, Alp, Bhp, Blp, rowA0, strideA, rowB0, strideB, k0base + 64, kvB, tid);

    // per-lane ldmatrix geometry
    int rr = lane & 7, sub = lane >> 3;
    int wm = (w & 1) * 64, wn = (w >> 1) * 32;
    int arow = wm + rr + (sub & 1) * 8;
    int acb0 = (sub >> 1) * 16;
    int brow = wn + rr + (sub >> 1) * 8;
    int bcb0 = (sub & 1) * 16;

    for (int kt = 0; kt < NKT; kt++){
        uint32_t st = sb + (uint32_t)(kt & 1) * STAGE_BYTES;
        if (kt + 1 < NKT) cpa_wait1(); else cpa_wait0();
        __syncthreads();
#pragma unroll
        for (int ks = 0; ks < 4; ks++){
            uint32_t ahf[4][4], alf[4][4], bhf[4][2], blf[4][2];
#pragma unroll
            for (int i = 0; i < 4; i++){
                uint32_t sa = swz((uint32_t)((arow + i*16)*128 + acb0 + ks*32));
                ldsm4(ahf[i][0], ahf[i][1], ahf[i][2], ahf[i][3], st + sa);
                ldsm4(alf[i][0], alf[i][1], alf[i][2], alf[i][3], st + 16384 + sa);
            }
#pragma unroll
            for (int j2 = 0; j2 < 2; j2++){
                uint32_t sa = swz((uint32_t)((brow + j2*16)*128 + bcb0 + ks*32));
                uint32_t r0, r1, r2, r3;
                ldsm4(r0, r1, r2, r3, st + 32768 + sa);
                bhf[j2*2][0] = r0; bhf[j2*2][1] = r1; bhf[j2*2+1][0] = r2; bhf[j2*2+1][1] = r3;
                ldsm4(r0, r1, r2, r3, st + 49152 + sa);
                blf[j2*2][0] = r0; blf[j2*2][1] = r1; blf[j2*2+1][0] = r2; blf[j2*2+1][1] = r3;
            }
#pragma unroll
            for (int i = 0; i < 4; i++)
#pragma unroll
                for (int j = 0; j < 4; j++){
                    mma_bf16(acc[i][j], ahf[i], bhf[j]);
                    mma_bf16(acc[i][j], ahf[i], blf[j]);
                    mma_bf16(acc[i][j], alf[i], bhf[j]);
                }
        }
        __syncthreads();
        if (kt + 2 < NKT)
            load_stageM(sb + (uint32_t)(kt & 1)*STAGE_BYTES, Ahp, Alp, Bhp, Blp,
                        rowA0, strideA, rowB0, strideB, k0base + (kt + 2)*64, kvB, tid);
    }

    // ---------------- epilogues ----------------
    int r0row = lane >> 2, c0 = (lane & 3) * 2;
    float* fb = (float*)dsm;   // 128 x 129 fp32 transpose buffer

    if (mode == 0){
        if (bz < 2){
            __nv_bfloat16* Dh = bz ? g_Kh : g_Qh;
            __nv_bfloat16* Dl = bz ? g_Kl : g_Ql;
#pragma unroll
            for (int i = 0; i < 4; i++)
#pragma unroll
                for (int j = 0; j < 4; j++)
#pragma unroll
                    for (int half = 0; half < 2; half++){
                        int row = m0 + wm + i*16 + r0row + half*8;
                        int col = n0 + wn + j*8 + c0;
                        __nv_bfloat16 h0, l0, h1, l1;
                        split2(acc[i][j][half*2], h0, l0);
                        split2(acc[i][j][half*2 + 1], h1, l1);
                        *(__nv_bfloat162*)&Dh[(size_t)row*Ee + col] = __nv_bfloat162{h0, h1};
                        *(__nv_bfloat162*)&Dl[(size_t)row*Ee + col] = __nv_bfloat162{l0, l1};
                    }
        } else {
            // V: transpose -> g_Vth/g_Vtl [b][n][t]
#pragma unroll
            for (int i = 0; i < 4; i++)
#pragma unroll
                for (int j = 0; j < 4; j++)
#pragma unroll
                    for (int half = 0; half < 2; half++){
                        int row = wm + i*16 + r0row + half*8;
                        int col = wn + j*8 + c0;
                        fb[row*129 + col]     = acc[i][j][half*2];
                        fb[row*129 + col + 1] = acc[i][j][half*2 + 1];
                    }
            __syncthreads();
            int b = m0 / Tt, t0 = m0 % Tt;
            for (int idx = tid; idx < 16384; idx += 256){
                int n = idx >> 7, t = idx & 127;
                __nv_bfloat16 h, l; split2(fb[t*129 + n], h, l);
                size_t o = (size_t)(b*Ee + n0 + n)*Tt + t0 + t;
                g_Vth[o] = h; g_Vtl[o] = l;
            }
        }
    } else if (mode == 2){
        int qk = bz & 1;
        if (qk == 0){
            // Qp: direct split store [bh][t][f]
#pragma unroll
            for (int i = 0; i < 4; i++)
#pragma unroll
                for (int j = 0; j < 4; j++)
#pragma unroll
                    for (int half = 0; half < 2; half++){
                        int row = wm + i*16 + r0row + half*8;
                        int col = wn + j*8 + c0;
                        __nv_bfloat16 h0, l0, h1, l1;
                        split2(expf(acc[i][j][half*2]) + EPS, h0, l0);
                        split2(expf(acc[i][j][half*2 + 1]) + EPS, h1, l1);
                        size_t o = (size_t)(bh*Tt + m0 + row)*Ff + n0 + col;
                        *(__nv_bfloat162*)&g_Qph[o] = __nv_bfloat162{h0, h1};
                        *(__nv_bfloat162*)&g_Qpl[o] = __nv_bfloat162{l0, l1};
                    }
        } else {
            // Kp: transpose -> [bh][f][t]
#pragma unroll
            for (int i = 0; i < 4; i++)
#pragma unroll
                for (int j = 0; j < 4; j++)
#pragma unroll
                    for (int half = 0; half < 2; half++){
                        int row = wm + i*16 + r0row + half*8;
                        int col = wn + j*8 + c0;
                        fb[row*129 + col]     = expf(acc[i][j][half*2]) + EPS;
                        fb[row*129 + col + 1] = expf(acc[i][j][half*2 + 1]) + EPS;
                    }
            __syncthreads();
            for (int idx = tid; idx < 16384; idx += 256){
                int f = idx >> 7, t = idx & 127;
                __nv_bfloat16 h, l; split2(fb[t*129 + f], h, l);
                size_t o = (size_t)(bh*Ff + n0 + f)*Tt + m0 + t;
                g_Kpth[o] = h; g_Kptl[o] = l;
            }
        }
    } else if (mode == 3){
        // kv: transpose C[f][n] -> atomicAdd g_KVt[bh][n][f]
#pragma unroll
        for (int i = 0; i < 4; i++)
#pragma unroll
            for (int j = 0; j < 4; j++)
#pragma unroll
                for (int half = 0; half < 2; half++){
                    int row = wm + i*16 + r0row + half*8;
                    int col = wn + j*8 + c0;
                    fb[row*129 + col]     = acc[i][j][half*2];
                    fb[row*129 + col + 1] = acc[i][j][half*2 + 1];
                }
        __syncthreads();
        for (int idx = tid; idx < 16384; idx += 256){
            int n = idx >> 7, f = idx & 127;
            atomicAdd(&g_KVt[(size_t)(bh*128 + n)*Ff + m0 + f], fb[f*129 + n]);
        }
    } else if (mode == 4){
        // attn: denom at col 64 (warps 4,5, j=0, lanes lane%4==0)
        if ((w == 4 || w == 5) && (lane & 3) == 0){
#pragma unroll
            for (int i = 0; i < 4; i++)
#pragma unroll
                for (int half = 0; half < 2; half++){
                    int row = wm + i*16 + r0row + half*8;
                    sden[row] = acc[i][0][half*2];
                }
        }
        __syncthreads();
        if (w < 4){
            int b = bh >> 4, h = bh & 15;
#pragma unroll
            for (int i = 0; i < 4; i++)
#pragma unroll
                for (int half = 0; half < 2; half++){
                    int row = wm + i*16 + r0row + half*8;
                    float inv = 1.0f / fmaxf(sden[row], 1e-6f);
#pragma unroll
                    for (int j = 0; j < 4; j++){
                        int col = wn + j*8 + c0;
                        __nv_bfloat16 h0, l0, h1, l1;
                        split2(acc[i][j][half*2] * inv, h0, l0);
                        split2(acc[i][j][half*2 + 1] * inv, h1, l1);
                        size_t o = (size_t)(b*Tt + m0 + row)*Ee + h*Dd + col;
                        *(__nv_bfloat162*)&g_ah[o] = __nv_bfloat162{h0, h1};
                        *(__nv_bfloat162*)&g_al[o] = __nv_bfloat162{l0, l1};
                    }
                }
        }
    } else {
        // mode 1: transpose, coalesced transposed store into out[b][Cc+n][t]
#pragma unroll
        for (int i = 0; i < 4; i++)
#pragma unroll
            for (int j = 0; j < 4; j++)
#pragma unroll
                for (int half = 0; half < 2; half++){
                    int row = wm + i*16 + r0row + half*8;
                    int col = wn + j*8 + c0;
                    fb[row*129 + col]     = acc[i][j][half*2];
                    fb[row*129 + col + 1] = acc[i][j][half*2 + 1];
                }
        __syncthreads();
        int b = m0 / Tt, t0 = m0 % Tt;
        for (int idx = tid; idx < 16384; idx += 256){
            int n = idx >> 7, t = idx & 127;
            outp[(size_t)b*CO*Tt + (size_t)(Cc + n0 + n)*Tt + t0 + t] = fb[t*129 + n];
        }
    }
}

// ================= launch =================
extern "C" void kernel_launch(void* const* d_in, const int* in_sizes, int n_in,
                              void* d_out, int out_size) {
    const float* x    = (const float*)d_in[0];
    const float* Wq   = (const float*)d_in[1];
    const float* Wk   = (const float*)d_in[2];
    const float* Wv   = (const float*)d_in[3];
    const float* Wo   = (const float*)d_in[4];
    const float* proj = (const float*)d_in[5];
    float* out = (float*)d_out;

    cudaFuncSetAttribute(k_mma, cudaFuncAttributeMaxDynamicSharedMemorySize, DSM_BYTES);

    k_zero<<<Bb*Hh*128*Ff/256, 256>>>();
    k_copy<<<Bb*Cc*Tt/4/256, 256>>>(x, out);
    k_prep_x<<<dim3(Tt/32, Cc/32, Bb), dim3(32, 8)>>>(x);
    k_prep_w<<<dim3(Ee/32, Cc/32), dim3(32, 8)>>>(Wq, 0, Cc);
    k_prep_w<<<dim3(Ee/32, Cc/32), dim3(32, 8)>>>(Wk, 1, Cc);
    k_prep_w<<<dim3(Ee/32, Cc/32), dim3(32, 8)>>>(Wv, 2, Cc);
    k_prep_w<<<dim3(Ee/32, Ee/32), dim3(32, 8)>>>(Wo, 3, Ee);
    k_prep_proj<<<(Ff*Dd + 255)/256, 256>>>(proj);
    k_prep_ones<<<16, 256>>>();

    // QKV: Q,K split out; V transposed split out
    k_mma<<<dim3(Bb*Tt/128, Ee/128, 3), 256, DSM_BYTES>>>(0, nullptr);
    // feat: Qp direct, Kp transposed
    k_mma<<<dim3(Tt/128, Ff/128, Bb*Hh*2), 256, DSM_BYTES>>>(2, nullptr);
    // kv (+Ksum via ones column): atomicAdd into g_KVt
    k_mma<<<dim3(Ff/128, 2, Bb*Hh), 256, DSM_BYTES>>>(3, nullptr);
    k_cvt_kv<<<Bb*Hh*128*Ff/256, 256>>>();
    // attn: numer/denom fused
    k_mma<<<dim3(Tt/128, 1, Bb*Hh), 256, DSM_BYTES>>>(4, nullptr);
    // Wo + concat transposed store
    k_mma<<<dim3(Bb*Tt/128, Ee/128, 1), 256, DSM_BYTES>>>(1, out);
}

// round 5
// speedup vs baseline: 2.9287x; 1.0725x over previous
#include <cuda_runtime.h>
#include <cuda_bf16.h>
#include <cstdint>
#include <math.h>

#define Bb 4
#define Cc 512
#define Tt 4096
#define Ee 1024
#define Hh 16
#define Dd 64
#define Ff 256
#define CO 1536
#define EPS 1e-6f

typedef __nv_bfloat16 bf;

// ---------------- scratch ----------------
__device__ __align__(1024) bf g_xh[Bb*Tt*Cc],  g_xl[Bb*Tt*Cc];
__device__ __align__(1024) bf g_Qh[Bb*Tt*Ee],  g_Ql[Bb*Tt*Ee];
__device__ __align__(1024) bf g_Kh[Bb*Tt*Ee],  g_Kl[Bb*Tt*Ee];
__device__ __align__(1024) bf g_Vth[Bb*Ee*Tt], g_Vtl[Bb*Ee*Tt];
__device__ __align__(1024) bf g_Wqh[Ee*Cc],    g_Wql[Ee*Cc];
__device__ __align__(1024) bf g_Wkh[Ee*Cc],    g_Wkl[Ee*Cc];
__device__ __align__(1024) bf g_Wvh[Ee*Cc],    g_Wvl[Ee*Cc];
__device__ __align__(1024) bf g_Woh[Ee*Ee],    g_Wol[Ee*Ee];
__device__ __align__(1024) bf g_ph[Ff*Dd],     g_pl[Ff*Dd];
__device__ __align__(1024) bf g_Qph[Bb*Hh*Tt*Ff], g_Qpl[Bb*Hh*Tt*Ff];
__device__ __align__(1024) bf g_Kpth[Bb*Hh*Ff*Tt], g_Kptl[Bb*Hh*Ff*Tt];
__device__ __align__(1024) bf g_ah[Bb*Tt*Ee],  g_al[Bb*Tt*Ee];
__device__ __align__(1024) bf g_KVth[Bb*Hh*64*Ff], g_KVtl[Bb*Hh*64*Ff];
__device__ float g_KVt[Bb*Hh*64*Ff];     // fp32 accum
__device__ float g_Ksum[Bb*Hh*Ff];       // fp32 accum

// ================= PTX helpers =================
__device__ __forceinline__ uint32_t s2u(const void* p){
    uint32_t a;
    asm("{ .reg .u64 t; cvta.to.shared.u64 t, %1; cvt.u32.u64 %0, t; }" : "=r"(a) : "l"(p));
    return a;
}
__device__ __forceinline__ uint32_t swz(uint32_t off){ return off ^ ((off >> 3) & 0x70); }

__device__ __forceinline__ void ldsm4(uint32_t& r0, uint32_t& r1, uint32_t& r2, uint32_t& r3, uint32_t addr){
    asm volatile("ldmatrix.sync.aligned.m8n8.x4.shared.b16 {%0,%1,%2,%3}, [%4];"
        : "=r"(r0), "=r"(r1), "=r"(r2), "=r"(r3) : "r"(addr));
}
__device__ __forceinline__ void mma_bf16(float* c, const uint32_t* a, const uint32_t* b){
    asm volatile("mma.sync.aligned.m16n8k16.row.col.f32.bf16.bf16.f32 "
        "{%0,%1,%2,%3}, {%4,%5,%6,%7}, {%8,%9}, {%0,%1,%2,%3};"
        : "+f"(c[0]), "+f"(c[1]), "+f"(c[2]), "+f"(c[3])
        : "r"(a[0]), "r"(a[1]), "r"(a[2]), "r"(a[3]), "r"(b[0]), "r"(b[1]));
}
__device__ __forceinline__ void cpa16(uint32_t s, const void* g){
    asm volatile("cp.async.cg.shared.global [%0], [%1], 16;" :: "r"(s), "l"(g));
}
__device__ __forceinline__ void cpa_commit(){ asm volatile("cp.async.commit_group;" ::: "memory"); }
__device__ __forceinline__ void cpa_wait0(){ asm volatile("cp.async.wait_group 0;" ::: "memory"); }
__device__ __forceinline__ void cpa_wait1(){ asm volatile("cp.async.wait_group 1;" ::: "memory"); }
__device__ __forceinline__ void cpa_wait2(){ asm volatile("cp.async.wait_group 2;" ::: "memory"); }

__device__ __forceinline__ void split2(float a, bf& h, bf& l){
    h = __float2bfloat16(a);
    l = __float2bfloat16(a - __bfloat162float(h));
}

// ================= small kernels =================
__global__ void k_zero() {
    int i = blockIdx.x * 256 + threadIdx.x;
    if (i < Bb*Hh*64*Ff) g_KVt[i] = 0.f;
    if (i < Bb*Hh*Ff)    g_Ksum[i] = 0.f;
}
__global__ void k_copy(const float* __restrict__ x, float* __restrict__ out) {
    int i = blockIdx.x * 256 + threadIdx.x;
    const int per_b = Cc * Tt / 4;
    int b = i / per_b, r = i % per_b;
    ((float4*)out)[(size_t)b*(CO*Tt/4) + r] = ((const float4*)x)[(size_t)b*per_b + r];
}
__global__ void k_prep_x(const float* __restrict__ x){
    __shared__ float tile[32][33];
    int b = blockIdx.z, t0 = blockIdx.x*32, c0 = blockIdx.y*32;
    int tx = threadIdx.x, ty = threadIdx.y;
    for (int i = ty; i < 32; i += 8)
        tile[i][tx] = x[((size_t)b*Cc + c0 + i)*Tt + t0 + tx];
    __syncthreads();
    for (int i = ty; i < 32; i += 8){
        bf hi, lo; split2(tile[tx][i], hi, lo);
        size_t o = ((size_t)b*Tt + t0 + i)*Cc + c0 + tx;
        g_xh[o] = hi; g_xl[o] = lo;
    }
}
__global__ void k_prep_w(const float* __restrict__ W, int widx, int Kd){
    const int Nd = Ee;
    bf *Dh, *Dl;
    if      (widx == 0){ Dh = g_Wqh; Dl = g_Wql; }
    else if (widx == 1){ Dh = g_Wkh; Dl = g_Wkl; }
    else if (widx == 2){ Dh = g_Wvh; Dl = g_Wvl; }
    else               { Dh = g_Woh; Dl = g_Wol; }
    __shared__ float tile[32][33];
    int n0 = blockIdx.x*32, k0 = blockIdx.y*32;
    int tx = threadIdx.x, ty = threadIdx.y;
    for (int i = ty; i < 32; i += 8)
        tile[i][tx] = W[(size_t)(k0 + i)*Nd + n0 + tx];
    __syncthreads();
    for (int i = ty; i < 32; i += 8){
        bf hi, lo; split2(tile[tx][i], hi, lo);
        size_t o = (size_t)(n0 + i)*Kd + k0 + tx;
        Dh[o] = hi; Dl[o] = lo;
    }
}
__global__ void k_prep_proj(const float* __restrict__ proj){
    int i = blockIdx.x * 256 + threadIdx.x;
    if (i < Ff*Dd){ bf hi, lo; split2(proj[i], hi, lo); g_ph[i] = hi; g_pl[i] = lo; }
}
__global__ void k_cvt_kv(){
    int i = blockIdx.x * 256 + threadIdx.x;
    if (i < Bb*Hh*64*Ff){ bf h, l; split2(g_KVt[i], h, l); g_KVth[i] = h; g_KVtl[i] = l; }
}

// ================= tile loaders =================
__device__ __forceinline__ void load_tile(uint32_t sbase, const bf* g, int row0, int stride, int k0, int tid){
#pragma unroll
    for (int i = 0; i < 4; i++){
        int idx = tid + i*256;
        int r = idx >> 3, kc = idx & 7;
        cpa16(sbase + swz((uint32_t)(r*128 + kc*16)), g + (size_t)(row0 + r)*stride + k0 + kc*8);
    }
}
template<int NBROWS>
__device__ __forceinline__ void load_stageT(uint32_t st,
    const bf* Ahp, const bf* Alp, const bf* Bhp, const bf* Blp,
    int rowA0, int sA, int rowB0, int sB, int k0, int tid){
    load_tile(st,         Ahp, rowA0, sA, k0, tid);
    load_tile(st + 16384, Alp, rowA0, sA, k0, tid);
    const uint32_t blo = 32768u + NBROWS*128u;
#pragma unroll
    for (int idx = tid; idx < NBROWS*8; idx += 256){
        int r = idx >> 3, kc = idx & 7;
        cpa16(st + 32768 + swz((uint32_t)(r*128 + kc*16)), Bhp + (size_t)(rowB0 + r)*sB + k0 + kc*8);
    }
#pragma unroll
    for (int idx = tid; idx < NBROWS*8; idx += 256){
        int r = idx >> 3, kc = idx & 7;
        cpa16(st + blo + swz((uint32_t)(r*128 + kc*16)), Blp + (size_t)(rowB0 + r)*sB + k0 + kc*8);
    }
    cpa_commit();
}

// ================= main MMA kernel (templated on mode) =================
// MODE 0: QKV   A=x[bt][c], B=W^T, out: z<2 split bf16 Q/K, z=2 V transposed split
// MODE 1: Wo    -> transposed fp32 store into out[b][Cc+n][t]
// MODE 3: kv    C[f][n]=Kp^T@V^T over T-chunk, N=64, atomicAdd transposed
// MODE 4: attn  N=64 numer + FFMA denom -> split bf16 attn
#define STAGE_BYTES 65536
#define MMA_DSM     196608

template<int MODE>
__global__ __launch_bounds__(256, 1) void k_mma(float* __restrict__ outp){
    constexpr int JMAX   = (MODE == 3 || MODE == 4) ? 2 : 4;
    constexpr int NBROWS = JMAX * 32;
    constexpr int NKT    = (MODE == 0) ? 8 : (MODE == 1) ? 16 : (MODE == 3) ? 32 : 4;

    extern __shared__ __align__(1024) char dsm[];
    __shared__ float sden[128];
    __shared__ float sKs[256];
    uint32_t sb = s2u(dsm);
    int tid = threadIdx.x, lane = tid & 31, w = tid >> 5;
    int bz = blockIdx.z;
    int m0 = blockIdx.x * 128, n0 = blockIdx.y * 128;

    const bf *Ahp, *Alp, *Bhp, *Blp;
    int rowA0 = 0, rowB0 = 0, strideA = 0, strideB = 0, k0base = 0;

    if (MODE == 0){
        Ahp = g_xh; Alp = g_xl;
        Bhp = bz == 0 ? g_Wqh : bz == 1 ? g_Wkh : g_Wvh;
        Blp = bz == 0 ? g_Wql : bz == 1 ? g_Wkl : g_Wvl;
        rowA0 = m0; strideA = Cc; rowB0 = n0; strideB = Cc;
    } else if (MODE == 1){
        Ahp = g_ah; Alp = g_al; Bhp = g_Woh; Blp = g_Wol;
        rowA0 = m0; strideA = Ee; rowB0 = n0; strideB = Ee;
    } else if (MODE == 3){
        Ahp = g_Kpth; Alp = g_Kptl;
        rowA0 = bz*Ff + m0; strideA = Tt;
        Bhp = g_Vth; Blp = g_Vtl;
        rowB0 = (bz >> 4)*Ee + (bz & 15)*Dd; strideB = Tt;
        k0base = blockIdx.y * 2048;
    } else {
        Ahp = g_Qph; Alp = g_Qpl;
        rowA0 = bz*Tt + m0; strideA = Ff;
        Bhp = g_KVth; Blp = g_KVtl;
        rowB0 = bz*64; strideB = Ff;
    }

    if (MODE == 4){
        if (tid < 128) sden[tid] = 0.f;
        sKs[tid] = g_Ksum[bz*Ff + tid];
    }

    float acc[4][JMAX][4];
#pragma unroll
    for (int i = 0; i < 4; i++)
#pragma unroll
        for (int j = 0; j < JMAX; j++)
#pragma unroll
            for (int c = 0; c < 4; c++) acc[i][j][c] = 0.f;

    load_stageT<NBROWS>(sb, Ahp, Alp, Bhp, Blp, rowA0, strideA, rowB0, strideB, k0base, tid);
    if (NKT > 1)
        load_stageT<NBROWS>(sb + STAGE_BYTES, Ahp, Alp, Bhp, Blp, rowA0, strideA, rowB0, strideB, k0base + 64, tid);

    int rr = lane & 7, sub = lane >> 3;
    int wm = (w & 1) * 64, wn = (w >> 1) * (JMAX * 8);
    int arow = wm + rr + (sub & 1) * 8;
    int acb0 = (sub >> 1) * 16;
    int brow = wn + rr + (sub >> 1) * 8;
    int bcb0 = (sub & 1) * 16;
    const uint32_t blo = 32768u + NBROWS*128u;

    for (int kt = 0; kt < NKT; kt++){
        uint32_t st = sb + (uint32_t)(kt % 3) * STAGE_BYTES;
        if (kt + 2 < NKT)
            load_stageT<NBROWS>(sb + (uint32_t)((kt + 2) % 3) * STAGE_BYTES,
                                Ahp, Alp, Bhp, Blp, rowA0, strideA, rowB0, strideB,
                                k0base + (kt + 2)*64, tid);
        int rem = NKT - 1 - kt;
        if (rem >= 2) cpa_wait2(); else if (rem == 1) cpa_wait1(); else cpa_wait0();
        __syncthreads();

#pragma unroll
        for (int ks = 0; ks < 4; ks++){
            uint32_t ahf[4][4], alf[4][4], bhf[JMAX][2], blf[JMAX][2];
#pragma unroll
            for (int i = 0; i < 4; i++){
                uint32_t sa = swz((uint32_t)((arow + i*16)*128 + acb0 + ks*32));
                ldsm4(ahf[i][0], ahf[i][1], ahf[i][2], ahf[i][3], st + sa);
                ldsm4(alf[i][0], alf[i][1], alf[i][2], alf[i][3], st + 16384 + sa);
            }
#pragma unroll
            for (int j2 = 0; j2 < JMAX/2; j2++){
                uint32_t sa = swz((uint32_t)((brow + j2*16)*128 + bcb0 + ks*32));
                uint32_t r0, r1, r2, r3;
                ldsm4(r0, r1, r2, r3, st + 32768 + sa);
                bhf[j2*2][0] = r0; bhf[j2*2][1] = r1; bhf[j2*2+1][0] = r2; bhf[j2*2+1][1] = r3;
                ldsm4(r0, r1, r2, r3, st + blo + sa);
                blf[j2*2][0] = r0; blf[j2*2][1] = r1; blf[j2*2+1][0] = r2; blf[j2*2+1][1] = r3;
            }
#pragma unroll
            for (int i = 0; i < 4; i++)
#pragma unroll
                for (int j = 0; j < JMAX; j++){
                    mma_bf16(acc[i][j], ahf[i], bhf[j]);
                    mma_bf16(acc[i][j], ahf[i], blf[j]);
                    mma_bf16(acc[i][j], alf[i], bhf[j]);
                }
        }
        if (MODE == 4){
            // denominator partial: row = tid&127 sums 32 f's of this k-tile
            int row = tid & 127, fh = (tid >> 7) * 32;
            const char* sp = dsm + (size_t)(kt % 3) * STAGE_BYTES;
            float part = 0.f;
#pragma unroll
            for (int jj = 0; jj < 32; jj++){
                int fl = fh + ((jj + lane) & 31);
                uint32_t off = swz((uint32_t)(row*128 + fl*2));
                float hi = __bfloat162float(*(const bf*)(sp + off));
                float lo = __bfloat162float(*(const bf*)(sp + 16384 + off));
                part += (hi + lo) * sKs[kt*64 + fl];
            }
            atomicAdd(&sden[row], part);
        }
        __syncthreads();
    }

    // ---------------- epilogues ----------------
    int r0row = lane >> 2, c0 = (lane & 3) * 2;
    float* fb = (float*)dsm;

    if (MODE == 0){
        if (bz < 2){
            bf* Dh = bz ? g_Kh : g_Qh;
            bf* Dl = bz ? g_Kl : g_Ql;
#pragma unroll
            for (int i = 0; i < 4; i++)
#pragma unroll
                for (int j = 0; j < 4; j++)
#pragma unroll
                    for (int half = 0; half < 2; half++){
                        int row = m0 + wm + i*16 + r0row + half*8;
                        int col = n0 + wn + j*8 + c0;
                        bf h0, l0, h1, l1;
                        split2(acc[i][j][half*2], h0, l0);
                        split2(acc[i][j][half*2 + 1], h1, l1);
                        *(__nv_bfloat162*)&Dh[(size_t)row*Ee + col] = __nv_bfloat162{h0, h1};
                        *(__nv_bfloat162*)&Dl[(size_t)row*Ee + col] = __nv_bfloat162{l0, l1};
                    }
        } else {
#pragma unroll
            for (int i = 0; i < 4; i++)
#pragma unroll
                for (int j = 0; j < 4; j++)
#pragma unroll
                    for (int half = 0; half < 2; half++){
                        int row = wm + i*16 + r0row + half*8;
                        int col = wn + j*8 + c0;
                        fb[row*129 + col]     = acc[i][j][half*2];
                        fb[row*129 + col + 1] = acc[i][j][half*2 + 1];
                    }
            __syncthreads();
            int b = m0 / Tt, t0 = m0 % Tt;
            for (int idx = tid; idx < 16384; idx += 256){
                int n = idx >> 7, t = idx & 127;
                bf h, l; split2(fb[t*129 + n], h, l);
                size_t o = (size_t)(b*Ee + n0 + n)*Tt + t0 + t;
                g_Vth[o] = h; g_Vtl[o] = l;
            }
        }
    } else if (MODE == 3){
#pragma unroll
        for (int i = 0; i < 4; i++)
#pragma unroll
            for (int j = 0; j < JMAX; j++)
#pragma unroll
                for (int half = 0; half < 2; half++){
                    int row = wm + i*16 + r0row + half*8;
                    int col = wn + j*8 + c0;
                    fb[row*129 + col]     = acc[i][j][half*2];
                    fb[row*129 + col + 1] = acc[i][j][half*2 + 1];
                }
        __syncthreads();
        for (int idx = tid; idx < 8192; idx += 256){
            int n = idx >> 7, f = idx & 127;
            atomicAdd(&g_KVt[((size_t)bz*64 + n)*Ff + m0 + f], fb[f*129 + n]);
        }
    } else if (MODE == 4){
        int b = bz >> 4, h = bz & 15;
#pragma unroll
        for (int i = 0; i < 4; i++)
#pragma unroll
            for (int half = 0; half < 2; half++){
                int row = wm + i*16 + r0row + half*8;
                float inv = 1.0f / fmaxf(sden[row], 1e-6f);
#pragma unroll
                for (int j = 0; j < JMAX; j++){
                    int col = wn + j*8 + c0;
                    bf h0, l0, h1, l1;
                    split2(acc[i][j][half*2] * inv, h0, l0);
                    split2(acc[i][j][half*2 + 1] * inv, h1, l1);
                    size_t o = (size_t)(b*Tt + m0 + row)*Ee + h*Dd + col;
                    *(__nv_bfloat162*)&g_ah[o] = __nv_bfloat162{h0, h1};
                    *(__nv_bfloat162*)&g_al[o] = __nv_bfloat162{l0, l1};
                }
            }
    } else {
#pragma unroll
        for (int i = 0; i < 4; i++)
#pragma unroll
            for (int j = 0; j < 4; j++)
#pragma unroll
                for (int half = 0; half < 2; half++){
                    int row = wm + i*16 + r0row + half*8;
                    int col = wn + j*8 + c0;
                    fb[row*129 + col]     = acc[i][j][half*2];
                    fb[row*129 + col + 1] = acc[i][j][half*2 + 1];
                }
        __syncthreads();
        int b = m0 / Tt, t0 = m0 % Tt;
        for (int idx = tid; idx < 16384; idx += 256){
            int n = idx >> 7, t = idx & 127;
            outp[(size_t)b*CO*Tt + (size_t)(Cc + n0 + n)*Tt + t0 + t] = fb[t*129 + n];
        }
    }
}

// ================= feature-map kernel: proj resident, 4 m-tiles / block =================
// Qp (qk=0): direct split store. Kp (qk=1): transpose + split store + Ksum fp32 atomics.
#define FEAT_DSM (32768 + 65536 + 67584)

__global__ __launch_bounds__(256, 1) void k_featm(){
    extern __shared__ __align__(1024) char dsm[];
    uint32_t sb = s2u(dsm);
    int tid = threadIdx.x, lane = tid & 31, w = tid >> 5;
    int qk = blockIdx.z & 1, bh = blockIdx.z >> 1;
    int m0 = blockIdx.x * 512, n0 = blockIdx.y * 128;

    const bf* Ahp = (qk ? g_Kh : g_Qh) + (bh & 15)*Dd;
    const bf* Alp = (qk ? g_Kl : g_Ql) + (bh & 15)*Dd;
    int rowA0 = (bh >> 4)*Tt + m0;

    // prologue: B (proj) + A tile 0 (group 0); A tile 1 (group 1)
    load_tile(sb,         g_ph, n0, Dd, 0, tid);
    load_tile(sb + 16384, g_pl, n0, Dd, 0, tid);
    load_tile(sb + 32768,         Ahp, rowA0, Ee, 0, tid);
    load_tile(sb + 32768 + 16384, Alp, rowA0, Ee, 0, tid);
    cpa_commit();
    load_tile(sb + 65536,         Ahp, rowA0 + 128, Ee, 0, tid);
    load_tile(sb + 65536 + 16384, Alp, rowA0 + 128, Ee, 0, tid);
    cpa_commit();

    int rr = lane & 7, sub = lane >> 3;
    int wm = (w & 1) * 64, wn = (w >> 1) * 32;
    int arow = wm + rr + (sub & 1) * 8;
    int acb0 = (sub >> 1) * 16;
    int brow = wn + rr + (sub >> 1) * 8;
    int bcb0 = (sub & 1) * 16;
    float* fb = (float*)(dsm + 32768 + 65536);   // 128 x 129+ transpose buffer

    for (int mi = 0; mi < 4; mi++){
        uint32_t stA = sb + 32768 + (uint32_t)(mi & 1) * 32768;
        if (mi < 3) cpa_wait1(); else cpa_wait0();
        __syncthreads();

        float acc[4][4][4];
#pragma unroll
        for (int i = 0; i < 4; i++)
#pragma unroll
            for (int j = 0; j < 4; j++)
#pragma unroll
                for (int c = 0; c < 4; c++) acc[i][j][c] = 0.f;

#pragma unroll
        for (int ks = 0; ks < 4; ks++){
            uint32_t ahf[4][4], alf[4][4], bhf[4][2], blf[4][2];
#pragma unroll
            for (int i = 0; i < 4; i++){
                uint32_t sa = swz((uint32_t)((arow + i*16)*128 + acb0 + ks*32));
                ldsm4(ahf[i][0], ahf[i][1], ahf[i][2], ahf[i][3], stA + sa);
                ldsm4(alf[i][0], alf[i][1], alf[i][2], alf[i][3], stA + 16384 + sa);
            }
#pragma unroll
            for (int j2 = 0; j2 < 2; j2++){
                uint32_t sa = swz((uint32_t)((brow + j2*16)*128 + bcb0 + ks*32));
                uint32_t r0, r1, r2, r3;
                ldsm4(r0, r1, r2, r3, sb + sa);
                bhf[j2*2][0] = r0; bhf[j2*2][1] = r1; bhf[j2*2+1][0] = r2; bhf[j2*2+1][1] = r3;
                ldsm4(r0, r1, r2, r3, sb + 16384 + sa);
                blf[j2*2][0] = r0; blf[j2*2][1] = r1; blf[j2*2+1][0] = r2; blf[j2*2+1][1] = r3;
            }
#pragma unroll
            for (int i = 0; i < 4; i++)
#pragma unroll
                for (int j = 0; j < 4; j++){
                    mma_bf16(acc[i][j], ahf[i], bhf[j]);
                    mma_bf16(acc[i][j], ahf[i], blf[j]);
                    mma_bf16(acc[i][j], alf[i], bhf[j]);
                }
        }
        __syncthreads();
        if (mi + 2 < 4){
            load_tile(stA,         Ahp, rowA0 + (mi + 2)*128, Ee, 0, tid);
            load_tile(stA + 16384, Alp, rowA0 + (mi + 2)*128, Ee, 0, tid);
            cpa_commit();
        }

        int r0row = lane >> 2, c0 = (lane & 3) * 2;
        if (qk == 0){
#pragma unroll
            for (int i = 0; i < 4; i++)
#pragma unroll
                for (int j = 0; j < 4; j++)
#pragma unroll
                    for (int half = 0; half < 2; half++){
                        int row = wm + i*16 + r0row + half*8;
                        int col = wn + j*8 + c0;
                        bf h0, l0, h1, l1;
                        split2(expf(acc[i][j][half*2]) + EPS, h0, l0);
                        split2(expf(acc[i][j][half*2 + 1]) + EPS, h1, l1);
                        size_t o = (size_t)(bh*Tt + m0 + mi*128 + row)*Ff + n0 + col;
                        *(__nv_bfloat162*)&g_Qph[o] = __nv_bfloat162{h0, h1};
                        *(__nv_bfloat162*)&g_Qpl[o] = __nv_bfloat162{l0, l1};
                    }
        } else {
#pragma unroll
            for (int i = 0; i < 4; i++)
#pragma unroll
                for (int j = 0; j < 4; j++)
#pragma unroll
                    for (int half = 0; half < 2; half++){
                        int row = wm + i*16 + r0row + half*8;
                        int col = wn + j*8 + c0;
                        fb[row*129 + col]     = expf(acc[i][j][half*2]) + EPS;
                        fb[row*129 + col + 1] = expf(acc[i][j][half*2 + 1]) + EPS;
                    }
            __syncthreads();
            // split-transpose store + Ksum accumulation
            for (int idx = tid; idx < 16384; idx += 256){
                int f = idx >> 7, t = idx & 127;
                bf h, l; split2(fb[t*129 + f], h, l);
                size_t o = (size_t)(bh*Ff + n0 + f)*Tt + m0 + mi*128 + t;
                g_Kpth[o] = h; g_Kptl[o] = l;
            }
            {
                int f = tid >> 1, th = tid & 1;
                float s = 0.f;
#pragma unroll 8
                for (int t = th*64; t < th*64 + 64; t++) s += fb[t*129 + f];
                atomicAdd(&g_Ksum[bh*Ff + n0 + f], s);
            }
        }
    }
}

// ================= launch =================
extern "C" void kernel_launch(void* const* d_in, const int* in_sizes, int n_in,
                              void* d_out, int out_size) {
    const float* x    = (const float*)d_in[0];
    const float* Wq   = (const float*)d_in[1];
    const float* Wk   = (const float*)d_in[2];
    const float* Wv   = (const float*)d_in[3];
    const float* Wo   = (const float*)d_in[4];
    const float* proj = (const float*)d_in[5];
    float* out = (float*)d_out;

    cudaFuncSetAttribute(k_mma<0>, cudaFuncAttributeMaxDynamicSharedMemorySize, MMA_DSM);
    cudaFuncSetAttribute(k_mma<1>, cudaFuncAttributeMaxDynamicSharedMemorySize, MMA_DSM);
    cudaFuncSetAttribute(k_mma<3>, cudaFuncAttributeMaxDynamicSharedMemorySize, MMA_DSM);
    cudaFuncSetAttribute(k_mma<4>, cudaFuncAttributeMaxDynamicSharedMemorySize, MMA_DSM);
    cudaFuncSetAttribute(k_featm,  cudaFuncAttributeMaxDynamicSharedMemorySize, FEAT_DSM);

    k_zero<<<(Bb*Hh*64*Ff + 255)/256, 256>>>();
    k_copy<<<Bb*Cc*Tt/4/256, 256>>>(x, out);
    k_prep_x<<<dim3(Tt/32, Cc/32, Bb), dim3(32, 8)>>>(x);
    k_prep_w<<<dim3(Ee/32, Cc/32), dim3(32, 8)>>>(Wq, 0, Cc);
    k_prep_w<<<dim3(Ee/32, Cc/32), dim3(32, 8)>>>(Wk, 1, Cc);
    k_prep_w<<<dim3(Ee/32, Cc/32), dim3(32, 8)>>>(Wv, 2, Cc);
    k_prep_w<<<dim3(Ee/32, Ee/32), dim3(32, 8)>>>(Wo, 3, Ee);
    k_prep_proj<<<(Ff*Dd + 255)/256, 256>>>(proj);

    k_mma<0><<<dim3(Bb*Tt/128, Ee/128, 3), 256, MMA_DSM>>>(nullptr);       // QKV
    k_featm<<<dim3(Tt/512, Ff/128, Bb*Hh*2), 256, FEAT_DSM>>>();           // Qp/Kp + Ksum
    k_mma<3><<<dim3(Ff/128, 2, Bb*Hh), 256, MMA_DSM>>>(nullptr);           // KV
    k_cvt_kv<<<(Bb*Hh*64*Ff + 255)/256, 256>>>();
    k_mma<4><<<dim3(Tt/128, 1, Bb*Hh), 256, MMA_DSM>>>(nullptr);           // attn
    k_mma<1><<<dim3(Bb*Tt/128, Ee/128, 1), 256, MMA_DSM>>>(out);           // Wo + concat
}